// round 10
// baseline (speedup 1.0000x reference)
#include <cuda_runtime.h>
#include <cuda_bf16.h>

// FrozenBNBStableEmbedding fused gather+dequant+LayerNorm.
// R10: R5 structure (warp-per-token, barrier-free) with v[32] ELIMINATED:
// two lookup passes over register-resident q[8] (pass1: accumulate,
// pass2: recompute + store). Regs ~50 -> 5 CTAs/SM (occ ~62% vs 42%).
// Kernel is latency-bound; more warps > more per-warp state.

#define D    1024
#define REP  16          // code-table replication
#define TPW  2           // tokens per warp
#define EPS  1e-5f

__global__ __launch_bounds__(256, 5) void emb_ln_kernel(
    const int*   __restrict__ x,
    const int*   __restrict__ w,
    const float* __restrict__ absmax,
    const float* __restrict__ code,
    const float* __restrict__ lnw,
    const float* __restrict__ lnb,
    float*       __restrict__ out,
    int n_tokens)
{
    __shared__ float  s_code[256 * REP];  // s_code[idx*REP + slot]
    __shared__ float4 s_lnw[256];
    __shared__ float4 s_lnb[256];

    const int tid  = threadIdx.x;
    const int warp = tid >> 5;
    const int lane = tid & 31;

    // Fill replicated code table + LN params (once per CTA)
    {
        const float c = code[tid];
        float4 cv = make_float4(c, c, c, c);
        float4* dst = reinterpret_cast<float4*>(&s_code[tid * REP]);
        dst[0] = cv; dst[1] = cv; dst[2] = cv; dst[3] = cv;
        s_lnw[tid] = __ldg(&reinterpret_cast<const float4*>(lnw)[tid]);
        s_lnb[tid] = __ldg(&reinterpret_cast<const float4*>(lnb)[tid]);
    }
    __syncthreads();

    const float* tab = &s_code[lane & (REP - 1)];
    const int warp_g = blockIdx.x * 8 + warp;

    #pragma unroll
    for (int t = 0; t < TPW; ++t) {
        const int tok = warp_g * TPW + t;
        if (tok >= n_tokens) break;

        const int   row   = __ldg(&x[tok]);
        const float scale = __ldg(&absmax[row >> 2]);
        const int4* wrow  = reinterpret_cast<const int4*>(w + (long long)row * D);

        // 8 independent 16B loads, front-batched: MLP = 8
        int4 q[8];
        #pragma unroll
        for (int i = 0; i < 8; ++i)
            q[i] = __ldg(&wrow[i * 32 + lane]);

        // Pass 1: lookups -> sum/sq (raw code domain, scale folded out).
        // 4-way split accumulators keep the FADD chains shallow.
        float sum0 = 0.f, sum1 = 0.f, sum2 = 0.f, sum3 = 0.f;
        float sq0 = 0.f, sq1 = 0.f, sq2 = 0.f, sq3 = 0.f;
        #pragma unroll
        for (int i = 0; i < 8; ++i) {
            float a = tab[(q[i].x & 255) * REP];
            float b = tab[(q[i].y & 255) * REP];
            float c = tab[(q[i].z & 255) * REP];
            float d = tab[(q[i].w & 255) * REP];
            sum0 += a; sum1 += b; sum2 += c; sum3 += d;
            sq0 += a*a; sq1 += b*b; sq2 += c*c; sq3 += d*d;
        }
        float sum = (sum0 + sum1) + (sum2 + sum3);
        float sq  = (sq0 + sq1) + (sq2 + sq3);

        // Butterfly reduction (sum & sq chains interleave)
        #pragma unroll
        for (int off = 16; off > 0; off >>= 1) {
            sum += __shfl_xor_sync(0xFFFFFFFFu, sum, off);
            sq  += __shfl_xor_sync(0xFFFFFFFFu, sq,  off);
        }

        const float mean_c = sum * (1.0f / D);
        const float var_c  = sq * (1.0f / D) - mean_c * mean_c;
        const float tscale = scale * rsqrtf(scale * scale * var_c + EPS);

        // Pass 2: re-lookup from q (still in regs) + fused affine + store
        float4* orow = reinterpret_cast<float4*>(out) + (long long)tok * (D / 4);
        #pragma unroll
        for (int i = 0; i < 8; ++i) {
            float a = tab[(q[i].x & 255) * REP];
            float b = tab[(q[i].y & 255) * REP];
            float c = tab[(q[i].z & 255) * REP];
            float d = tab[(q[i].w & 255) * REP];
            const float4 gw = s_lnw[i * 32 + lane];
            const float4 gb = s_lnb[i * 32 + lane];
            float4 o;
            o.x = (a - mean_c) * tscale * gw.x + gb.x;
            o.y = (b - mean_c) * tscale * gw.y + gb.y;
            o.z = (c - mean_c) * tscale * gw.z + gb.z;
            o.w = (d - mean_c) * tscale * gw.w + gb.w;
            __stcs(&orow[i * 32 + lane], o);
        }
    }
}

extern "C" void kernel_launch(void* const* d_in, const int* in_sizes, int n_in,
                              void* d_out, int out_size)
{
    const int*   x      = (const int*)d_in[0];
    const int*   w      = (const int*)d_in[1];
    const float* absmax = (const float*)d_in[2];
    const float* code   = (const float*)d_in[3];
    const float* lnw    = (const float*)d_in[4];
    const float* lnb    = (const float*)d_in[5];
    float*       out    = (float*)d_out;

    const int n_tokens = in_sizes[0];                     // 16384
    const int tokens_per_cta = 8 * TPW;                   // 16
    const int grid = (n_tokens + tokens_per_cta - 1) / tokens_per_cta;  // 1024
    emb_ln_kernel<<<grid, 256>>>(x, w, absmax, code, lnw, lnb, out, n_tokens);
}

// round 11
// speedup vs baseline: 1.0102x; 1.0102x over previous
#include <cuda_runtime.h>
#include <cuda_bf16.h>

// FrozenBNBStableEmbedding fused gather+dequant+LayerNorm.
// R11: R5 champion structure (warp-per-token, barrier-free, v[32], LN params
// from smem) + REP=32 fully-replicated code table: s_code[idx*32+lane] puts
// every lane in its own bank -> provably conflict-free lookups (48->32 wf),
// + scale folded into stats (fewer FMULs). Regs stay ~64 (occ ~42%).

#define D    1024
#define REP  32          // full per-lane replication: bank == lane
#define TPW  2           // tokens per warp
#define EPS  1e-5f

__global__ __launch_bounds__(256) void emb_ln_kernel(
    const int*   __restrict__ x,
    const int*   __restrict__ w,
    const float* __restrict__ absmax,
    const float* __restrict__ code,
    const float* __restrict__ lnw,
    const float* __restrict__ lnb,
    float*       __restrict__ out,
    int n_tokens)
{
    __shared__ float  s_code[256 * REP];  // 32KB: s_code[idx*32 + lane]
    __shared__ float4 s_lnw[256];
    __shared__ float4 s_lnb[256];

    const int tid  = threadIdx.x;
    const int warp = tid >> 5;
    const int lane = tid & 31;

    // Fill replicated code table (32 copies) + LN params (once per CTA)
    {
        const float c = code[tid];
        float4 cv = make_float4(c, c, c, c);
        float4* dst = reinterpret_cast<float4*>(&s_code[tid * REP]);
        #pragma unroll
        for (int i = 0; i < 8; ++i) dst[i] = cv;
        s_lnw[tid] = __ldg(&reinterpret_cast<const float4*>(lnw)[tid]);
        s_lnb[tid] = __ldg(&reinterpret_cast<const float4*>(lnb)[tid]);
    }
    __syncthreads();

    // Per-lane private column of the table: address = idx*32 + lane,
    // bank = (idx*32 + lane) & 31 = lane  ->  conflict-free always.
    const float* tab = &s_code[lane];
    const int warp_g = blockIdx.x * 8 + warp;

    #pragma unroll
    for (int t = 0; t < TPW; ++t) {
        const int tok = warp_g * TPW + t;
        if (tok >= n_tokens) break;

        const int   row   = __ldg(&x[tok]);
        const float scale = __ldg(&absmax[row >> 2]);
        const int4* wrow  = reinterpret_cast<const int4*>(w + (long long)row * D);

        // 8 independent 16B loads, front-batched: MLP = 8
        int4 q[8];
        #pragma unroll
        for (int i = 0; i < 8; ++i)
            q[i] = __ldg(&wrow[i * 32 + lane]);

        // Lookups in raw-code domain (scale folded out); split accumulators
        float v[32];
        float sum0 = 0.f, sum1 = 0.f, sum2 = 0.f, sum3 = 0.f;
        float sq0 = 0.f, sq1 = 0.f, sq2 = 0.f, sq3 = 0.f;
        #pragma unroll
        for (int i = 0; i < 8; ++i) {
            float a = tab[(q[i].x & 255) * REP];
            float b = tab[(q[i].y & 255) * REP];
            float c = tab[(q[i].z & 255) * REP];
            float d = tab[(q[i].w & 255) * REP];
            v[i*4+0] = a; v[i*4+1] = b; v[i*4+2] = c; v[i*4+3] = d;
            sum0 += a; sum1 += b; sum2 += c; sum3 += d;
            sq0 += a*a; sq1 += b*b; sq2 += c*c; sq3 += d*d;
        }
        float sum = (sum0 + sum1) + (sum2 + sum3);
        float sq  = (sq0 + sq1) + (sq2 + sq3);

        // Butterfly reduction (sum & sq chains interleave)
        #pragma unroll
        for (int off = 16; off > 0; off >>= 1) {
            sum += __shfl_xor_sync(0xFFFFFFFFu, sum, off);
            sq  += __shfl_xor_sync(0xFFFFFFFFu, sq,  off);
        }

        const float mean_c = sum * (1.0f / D);
        const float var_c  = sq * (1.0f / D) - mean_c * mean_c;
        const float tscale = scale * rsqrtf(scale * scale * var_c + EPS);

        float4* orow = reinterpret_cast<float4*>(out) + (long long)tok * (D / 4);
        #pragma unroll
        for (int i = 0; i < 8; ++i) {
            const float4 gw = s_lnw[i * 32 + lane];
            const float4 gb = s_lnb[i * 32 + lane];
            float4 o;
            o.x = (v[i*4+0] - mean_c) * tscale * gw.x + gb.x;
            o.y = (v[i*4+1] - mean_c) * tscale * gw.y + gb.y;
            o.z = (v[i*4+2] - mean_c) * tscale * gw.z + gb.z;
            o.w = (v[i*4+3] - mean_c) * tscale * gw.w + gb.w;
            __stcs(&orow[i * 32 + lane], o);
        }
    }
}

extern "C" void kernel_launch(void* const* d_in, const int* in_sizes, int n_in,
                              void* d_out, int out_size)
{
    const int*   x      = (const int*)d_in[0];
    const int*   w      = (const int*)d_in[1];
    const float* absmax = (const float*)d_in[2];
    const float* code   = (const float*)d_in[3];
    const float* lnw    = (const float*)d_in[4];
    const float* lnb    = (const float*)d_in[5];
    float*       out    = (float*)d_out;

    const int n_tokens = in_sizes[0];                     // 16384
    const int tokens_per_cta = 8 * TPW;                   // 16
    const int grid = (n_tokens + tokens_per_cta - 1) / tokens_per_cta;  // 1024
    emb_ln_kernel<<<grid, 256>>>(x, w, absmax, code, lnw, lnb, out, n_tokens);
}